// round 13
// baseline (speedup 1.0000x reference)
#include <cuda_runtime.h>
#include <cuda.h>
#include <cuda_fp16.h>
#include <cuda_bf16.h>
#include <cstdint>

#define MDIM 1024
#define KDIM 8192
#define NDIM 8192
#define KW   512

#if defined(__CUDA_ARCH__) && (defined(__CUDA_ARCH_FEAT_SM103_ALL) || \
                               defined(__CUDA_ARCH_FEAT_SM100_ALL) || \
     (defined(__CUDA_ARCH_FAMILY_SPECIFIC__) && (__CUDA_ARCH_FAMILY_SPECIFIC__ >= 1000)))
#define TC_PATH 1
#else
#define TC_PATH 0
#endif

__device__ int g_dtype;                                        // 0=fp16 1=fp32 2=bf16
__device__ __align__(128) __half g_x16[(size_t)MDIM * KDIM];   // 16 MB

// ---------------------------------------------------------------- helpers
__device__ __forceinline__ uint32_t smem_u32(const void* p) {
    uint32_t a;
    asm("{ .reg .u64 t; cvta.to.shared.u64 t, %1; cvt.u32.u64 %0, t; }"
        : "=r"(a) : "l"(p));
    return a;
}
__device__ __forceinline__ void cpa16(uint32_t dst, const void* src) {
    asm volatile("cp.async.cg.shared.global [%0], [%1], 16;" :: "r"(dst), "l"(src));
}

// ---------------------------------------------------------------- pre-passes
__global__ void detect_dtype_kernel(const uint32_t* __restrict__ xw) {
    int lane = threadIdx.x & 31;
    int cntA = 0, cntB = 0;
    for (int i = lane; i < 1024; i += 32) {
        uint32_t b1 = (xw[i] >> 8) & 0x7Fu;
        cntA += (b1 >= 0x18u && b1 <= 0x4Cu) ? 1 : 0;
        cntB += (b1 >= 0x3Bu && b1 <= 0x41u) ? 1 : 0;
    }
#pragma unroll
    for (int o = 16; o; o >>= 1) {
        cntA += __shfl_down_sync(0xFFFFFFFFu, cntA, o);
        cntB += __shfl_down_sync(0xFFFFFFFFu, cntB, o);
    }
    if (lane == 0) {
        int dt;
        if (cntA < 768)      dt = 1;
        else if (cntB > 716) dt = 2;
        else                 dt = 0;
        g_dtype = dt;
    }
}

__global__ void __launch_bounds__(256)
convert_x_kernel(const void* __restrict__ xv) {
    int dt = g_dtype;
    size_t base = ((size_t)blockIdx.x * 256 + threadIdx.x) * 8;
    uint4 o;
    if (dt == 0) {
        o = *(const uint4*)((const __half*)xv + base);
    } else if (dt == 1) {
        const float4* f = (const float4*)xv;
        float4 v0 = f[base / 4], v1 = f[base / 4 + 1];
        __half2 h0 = __floats2half2_rn(v0.x, v0.y), h1 = __floats2half2_rn(v0.z, v0.w);
        __half2 h2 = __floats2half2_rn(v1.x, v1.y), h3 = __floats2half2_rn(v1.z, v1.w);
        o = make_uint4(*(uint32_t*)&h0, *(uint32_t*)&h1,
                       *(uint32_t*)&h2, *(uint32_t*)&h3);
    } else {
        uint4 bi = *(const uint4*)((const __nv_bfloat16*)xv + base);
        const __nv_bfloat16* bb = (const __nv_bfloat16*)&bi;
        __align__(16) __half hvx[8];
#pragma unroll
        for (int j = 0; j < 8; j++) hvx[j] = __float2half_rn(__bfloat162float(bb[j]));
        o = *(uint4*)hvx;
    }
    *(uint4*)&g_x16[base] = o;
}

// decode one packed word -> 8 uint32 (16 fp16) via PRMT
__device__ __forceinline__ void decode_word(uint32_t vv, uint32_t* hv) {
#pragma unroll
    for (int i = 0; i < 8; i++) {
        uint32_t t = vv >> (4 * i);
        uint32_t sel = 0x0404u | ((t & 3u) << 4) | ((t & 12u) << 10);
        hv[i] = __byte_perm(0x42003C00u, 0u, sel);   // 0->0x00 1->0x3C 3->0x42
    }
}

// ============================================================================
// Path A: legacy HMMA fallback (plain-sm_103 device pass only)
// ============================================================================
#define HBM 128
#define HBN 128
#define HBK 64
#define HNTH 256
#define LDSH 72
#define HSMEM_BYTES 73728

__global__ void __launch_bounds__(HNTH, 2)
crystal_hmma_kernel(const int* __restrict__ pw, const void* __restrict__ biasv,
                    void* __restrict__ outv)
{
#if !TC_PATH
    extern __shared__ char dynsmem[];
    __half* As = (__half*)dynsmem;
    __half* Bs = As + 2 * HBM * LDSH;

    const int tid  = threadIdx.x;
    const int lane = tid & 31;
    const int warp = tid >> 5;
    const int wm   = warp & 1;
    const int wn   = warp >> 1;

    const int m0 = blockIdx.y * HBM;
    const int n0 = blockIdx.x * HBN;

    const uint32_t as_base = smem_u32(As);
    const uint32_t bs_base = smem_u32(Bs);

    const int brow  = tid >> 1;
    const int bpair = tid & 1;

    float acc[4][4][4];
#pragma unroll
    for (int i = 0; i < 4; i++)
#pragma unroll
        for (int j = 0; j < 4; j++)
#pragma unroll
            for (int r = 0; r < 4; r++) acc[i][j][r] = 0.f;

    int2 bst;

#define H_LOAD_A(buf, kt)                                                         \
    {                                                                             \
        _Pragma("unroll")                                                         \
        for (int p = 0; p < 4; p++) {                                             \
            int idx = tid + p * HNTH;                                             \
            int row = idx >> 3, c = idx & 7;                                      \
            const __half* srcA = g_x16 + (size_t)(m0 + row) * KDIM + (kt) * HBK + c * 8; \
            uint32_t dstA = as_base + (uint32_t)((((buf) * HBM + row) * LDSH + c * 8) * 2); \
            cpa16(dstA, srcA);                                                    \
        }                                                                         \
        asm volatile("cp.async.commit_group;");                                   \
    }

#define H_DECODE_B(buf)                                                           \
    {                                                                             \
        uint32_t vals[2] = { (uint32_t)bst.x, (uint32_t)bst.y };                  \
        _Pragma("unroll")                                                         \
        for (int w = 0; w < 2; w++) {                                             \
            uint32_t hv[8];                                                       \
            decode_word(vals[w], hv);                                             \
            uint4* dst = (uint4*)(Bs + (((buf) * HBN + brow) * LDSH + bpair * 32 + w * 16)); \
            dst[0] = make_uint4(hv[0], hv[1], hv[2], hv[3]);                      \
            dst[1] = make_uint4(hv[4], hv[5], hv[6], hv[7]);                      \
        }                                                                         \
    }

#define H_LOAD_B(kt) \
    bst = *(const int2*)(pw + (size_t)(n0 + brow) * KW + (kt) * 4 + bpair * 2);

    H_LOAD_B(0);
    H_LOAD_A(0, 0);
    H_DECODE_B(0);
    asm volatile("cp.async.wait_group 0;");
    __syncthreads();

    const int NK = KDIM / HBK;
    for (int kt = 0; kt < NK; kt++) {
        const int buf = kt & 1;
        const bool nxt = (kt + 1 < NK);
        if (nxt) {
            H_LOAD_A(buf ^ 1, kt + 1);
            H_LOAD_B(kt + 1);
        }

        const int mbase = wm * 64;
        const int nbase = wn * 32;
#pragma unroll
        for (int ks = 0; ks < 4; ks++) {
            uint32_t a[4][4];
#pragma unroll
            for (int mi = 0; mi < 4; mi++) {
                int row = mbase + mi * 16 + (lane & 15);
                int col = ks * 16 + ((lane >> 4) << 3);
                uint32_t addr = as_base + (uint32_t)(((buf * HBM + row) * LDSH + col) * 2);
                asm volatile(
                    "ldmatrix.sync.aligned.m8n8.x4.shared.b16 {%0,%1,%2,%3}, [%4];"
                    : "=r"(a[mi][0]), "=r"(a[mi][1]), "=r"(a[mi][2]), "=r"(a[mi][3])
                    : "r"(addr) : "memory");
            }
            uint32_t b[4][2];
#pragma unroll
            for (int ni = 0; ni < 2; ni++) {
                int q = lane >> 3, r = lane & 7;
                int row = nbase + ni * 16 + ((q >> 1) << 3) + r;
                int col = ks * 16 + ((q & 1) << 3);
                uint32_t addr = bs_base + (uint32_t)(((buf * HBN + row) * LDSH + col) * 2);
                uint32_t r0, r1, r2, r3;
                asm volatile(
                    "ldmatrix.sync.aligned.m8n8.x4.shared.b16 {%0,%1,%2,%3}, [%4];"
                    : "=r"(r0), "=r"(r1), "=r"(r2), "=r"(r3)
                    : "r"(addr) : "memory");
                b[2 * ni][0] = r0;     b[2 * ni][1] = r1;
                b[2 * ni + 1][0] = r2; b[2 * ni + 1][1] = r3;
            }
#pragma unroll
            for (int mi = 0; mi < 4; mi++) {
#pragma unroll
                for (int nj = 0; nj < 4; nj++) {
                    asm volatile(
                        "mma.sync.aligned.m16n8k16.row.col.f32.f16.f16.f32 "
                        "{%0,%1,%2,%3}, {%4,%5,%6,%7}, {%8,%9}, {%0,%1,%2,%3};"
                        : "+f"(acc[mi][nj][0]), "+f"(acc[mi][nj][1]),
                          "+f"(acc[mi][nj][2]), "+f"(acc[mi][nj][3])
                        : "r"(a[mi][0]), "r"(a[mi][1]), "r"(a[mi][2]), "r"(a[mi][3]),
                          "r"(b[nj][0]), "r"(b[nj][1]));
                }
            }
        }
        if (nxt) {
            H_DECODE_B(buf ^ 1);
            asm volatile("cp.async.wait_group 0;");
        }
        __syncthreads();
    }

    const int dt = g_dtype;
    const int g  = lane >> 2;
    const int tq = lane & 3;
#pragma unroll
    for (int nj = 0; nj < 4; nj++) {
        int ncol = n0 + wn * 32 + nj * 8 + tq * 2;
        __half hb0, hb1;
        if (dt == 1) {
            hb0 = __float2half_rn(((const float*)biasv)[ncol]);
            hb1 = __float2half_rn(((const float*)biasv)[ncol + 1]);
        } else if (dt == 2) {
            hb0 = __float2half_rn(__bfloat162float(((const __nv_bfloat16*)biasv)[ncol]));
            hb1 = __float2half_rn(__bfloat162float(((const __nv_bfloat16*)biasv)[ncol + 1]));
        } else {
            __half2 b2 = *(const __half2*)((const __half*)biasv + ncol);
            hb0 = __low2half(b2); hb1 = __high2half(b2);
        }
#pragma unroll
        for (int mi = 0; mi < 4; mi++) {
            int r0 = m0 + wm * 64 + mi * 16 + g;
#pragma unroll
            for (int hr = 0; hr < 2; hr++) {
                int rr = r0 + hr * 8;
                __half o0 = __hadd(__float2half_rn(acc[mi][nj][hr * 2 + 0]), hb0);
                __half o1 = __hadd(__float2half_rn(acc[mi][nj][hr * 2 + 1]), hb1);
                if (dt == 1) {
                    float* of = (float*)outv;
                    of[(size_t)rr * NDIM + ncol]     = __half2float(o0);
                    of[(size_t)rr * NDIM + ncol + 1] = __half2float(o1);
                } else if (dt == 2) {
                    __nv_bfloat16* ob = (__nv_bfloat16*)outv;
                    ob[(size_t)rr * NDIM + ncol]     = __float2bfloat16(__half2float(o0));
                    ob[(size_t)rr * NDIM + ncol + 1] = __float2bfloat16(__half2float(o1));
                } else {
                    __half* oh = (__half*)outv;
                    *(__half2*)(oh + (size_t)rr * NDIM + ncol) = __halves2half2(o0, o1);
                }
            }
        }
    }
#endif  // !TC_PATH
}

// ============================================================================
// Path B: cta_group::2 — pair computes 256x256; per-CTA A 128 rows (TMA) +
// B 128 rows (PRMT decode). 4-stage ring.
// ============================================================================
#define BK 64
#define NTILES 128
#define STAGES 4
#define NTH 320                  // warps 0-7 B decode, 8 TMA, 9 mma(leader)

#define SM_TMEMPTR 0
#define SM_FULL0   8             // 4 x 8B (leader-side aggregate)
#define SM_EMPTY0  40            // 4 x 8B (per-CTA, multicast commit)
#define SM_AFULL0  72            // 4 x 8B (local TMA completion)
#define SM_FINAL   104
#define SM_STAGE0  1024
#define STAGE_BYTES 32768        // A 16KB + B 16KB
#define SM_BOFF    16384
#define SMEM_TOTAL (1024 + STAGES * STAGE_BYTES)   // 132096
#define A_TX_BYTES 16384

#define TMEM_COLS 256
// cg2 kind::f16: dtype F32 (bit4), atype/btype fp16 (0), N=256 -> 32<<17, M=256 -> 16<<24
#define IDESC_CG2 ((1u << 4) | (32u << 17) | (16u << 24))

static constexpr uint64_t DESC_BASE_SW128 =
    (uint64_t(2) << 61) | (uint64_t(1) << 46) | (uint64_t(64) << 32) | (uint64_t(1) << 16);

#if TC_PATH
__device__ __forceinline__ uint32_t elect1() {
    uint32_t pred;
    asm volatile("{\n\t.reg .pred p;\n\telect.sync _|p, 0xFFFFFFFF;\n\t"
                 "selp.b32 %0, 1, 0, p;\n\t}" : "=r"(pred));
    return pred;
}
__device__ __forceinline__ uint32_t ctarank() {
    uint32_t r;
    asm("mov.u32 %0, %%cluster_ctarank;" : "=r"(r));
    return r;
}
__device__ __forceinline__ void mbar_init(uint32_t a, uint32_t c) {
    asm volatile("mbarrier.init.shared.b64 [%0], %1;" :: "r"(a), "r"(c) : "memory");
}
__device__ __forceinline__ void mbar_wait(uint32_t a, uint32_t parity) {
    uint32_t done;
    asm volatile("{\n\t.reg .pred p;\n\t"
                 "mbarrier.try_wait.parity.acquire.cta.shared::cta.b64 p, [%1], %2;\n\t"
                 "selp.b32 %0, 1, 0, p;\n\t}"
                 : "=r"(done) : "r"(a), "r"(parity) : "memory");
    if (!done) {
        asm volatile("{\n\t.reg .pred P1;\n\t"
                     "WL%=:\n\t"
                     "mbarrier.try_wait.parity.acquire.cta.shared::cta.b64 P1, [%0], %1, 0x989680;\n\t"
                     "@P1 bra.uni WD%=;\n\t"
                     "bra.uni WL%=;\n\t"
                     "WD%=:\n\t}"
                     :: "r"(a), "r"(parity) : "memory");
    }
}
// arrive on cluster-rank-0's mbarrier at the same smem offset
__device__ __forceinline__ void mbar_arrive_rank0(uint32_t a) {
    asm volatile("{\n\t.reg .b32 r;\n\tmapa.shared::cluster.u32 r, %0, 0;\n\t"
                 "mbarrier.arrive.shared::cluster.b64 _, [r];\n\t}"
                 :: "r"(a) : "memory");
}
__device__ __forceinline__ void mma_f16_cg2(uint32_t d, uint64_t ad, uint64_t bd,
                                            uint32_t idesc, uint32_t en) {
    asm volatile("{\n\t.reg .pred p;\n\tsetp.ne.u32 p, %4, 0;\n\t"
                 "tcgen05.mma.cta_group::2.kind::f16 [%0], %1, %2, %3, "
                 "{%5,%5,%5,%5,%5,%5,%5,%5}, p;\n\t}"
                 :: "r"(d), "l"(ad), "l"(bd), "r"(idesc), "r"(en), "r"(0u) : "memory");
}
#endif

__global__ void __launch_bounds__(NTH, 1)
#if TC_PATH
__cluster_dims__(2, 1, 1)
#endif
crystal_tc_kernel(const __grid_constant__ CUtensorMap tmap,
                  const int* __restrict__ pw, const void* __restrict__ biasv,
                  void* __restrict__ outv)
{
#if TC_PATH
    extern __shared__ char dynsmem[];
    const uint32_t sb = smem_u32(dynsmem);
    const int tid  = threadIdx.x;
    const int wid  = tid >> 5;
    const int lane = tid & 31;
    const uint32_t rank = ctarank();

    const int m0 = (blockIdx.x >> 1) * 256;   // pair M origin
    const int n0 = blockIdx.y * 256;

    if (tid == 0) {
#pragma unroll
        for (int s = 0; s < STAGES; s++) {
            mbar_init(sb + SM_FULL0  + s * 8, 18);   // 16 B leaders + 2 TMA relays
            mbar_init(sb + SM_EMPTY0 + s * 8, 1);    // multicast commit
            mbar_init(sb + SM_AFULL0 + s * 8, 1);    // local TMA expect_tx
        }
        mbar_init(sb + SM_FINAL, 1);
    }
    if (wid == 8) {
        asm volatile("tcgen05.alloc.cta_group::2.sync.aligned.shared::cta.b32 [%0], %1;"
                     :: "r"(sb + SM_TMEMPTR), "r"((uint32_t)TMEM_COLS) : "memory");
    }
    __syncthreads();
    uint32_t tmem_base;
    asm volatile("ld.shared.b32 %0, [%1];" : "=r"(tmem_base) : "r"(sb + SM_TMEMPTR));

    // all mbarriers + TMEM alloc visible cluster-wide before any cross-CTA traffic
    asm volatile("barrier.cluster.arrive.aligned;" ::: "memory");
    asm volatile("barrier.cluster.wait.aligned;" ::: "memory");

    if (wid < 8) {
        // ---- B decode producers: 256 threads, rows n0 + rank*128 + [0,128) --
        const int brow  = tid >> 1;          // 0..127 local row
        const int bpair = tid & 1;
        const size_t browg = (size_t)(n0 + (int)rank * 128 + brow) * KW;
        int2 bcur = *(const int2*)(pw + browg + bpair * 2);

        for (int p = 0; p < NTILES; p++) {
            const int s = p & 3;
            const int q = p >> 2;
            int2 bnext = make_int2(0, 0);
            if (p + 1 < NTILES)
                bnext = *(const int2*)(pw + browg + (p + 1) * 4 + bpair * 2);
            if (p >= STAGES)
                mbar_wait(sb + SM_EMPTY0 + s * 8, (q - 1) & 1);
            const uint32_t bbase = sb + SM_STAGE0 + s * STAGE_BYTES + SM_BOFF + brow * 128;
            const uint32_t vals[2] = { (uint32_t)bcur.x, (uint32_t)bcur.y };
#pragma unroll
            for (int w = 0; w < 2; w++) {
                uint32_t hv[8];
                decode_word(vals[w], hv);
#pragma unroll
                for (int h = 0; h < 2; h++) {
                    int u = bpair * 4 + w * 2 + h;
                    uint32_t dst = bbase + ((u ^ (brow & 7)) << 4);
                    asm volatile("st.shared.v4.b32 [%0], {%1,%2,%3,%4};"
                                 :: "r"(dst), "r"(hv[4*h]), "r"(hv[4*h+1]),
                                    "r"(hv[4*h+2]), "r"(hv[4*h+3]) : "memory");
                }
            }
            asm volatile("fence.proxy.async;" ::: "memory");
            __syncwarp();
            if (lane == 0) mbar_arrive_rank0(sb + SM_FULL0 + s * 8);
            bcur = bnext;
        }
    } else if (wid == 8) {
        // ---- TMA warp: A rows m0 + rank*128 + [0,128), pipelined relay ------
        if (elect1()) {
            const uint64_t tm = (uint64_t)&tmap;
            const int arow = m0 + (int)rank * 128;
            for (int p = 0; p <= NTILES; p++) {
                if (p < NTILES) {
                    const int s = p & 3;
                    if (p >= STAGES)
                        mbar_wait(sb + SM_EMPTY0 + s * 8, ((p >> 2) - 1) & 1);
                    const uint32_t af = sb + SM_AFULL0 + s * 8;
                    asm volatile("mbarrier.arrive.expect_tx.shared.b64 _, [%0], %1;"
                                 :: "r"(af), "r"((uint32_t)A_TX_BYTES) : "memory");
                    const uint32_t stg = sb + SM_STAGE0 + s * STAGE_BYTES;
                    asm volatile(
                        "cp.async.bulk.tensor.2d.shared::cta.global.tile.mbarrier::complete_tx::bytes "
                        "[%0], [%1, {%2, %3}], [%4];"
                        :: "r"(stg), "l"(tm), "r"(p * BK), "r"(arow), "r"(af) : "memory");
                }
                if (p >= 1) {
                    const int pc = p - 1;
                    const int s = pc & 3;
                    mbar_wait(sb + SM_AFULL0 + s * 8, (pc >> 2) & 1);
                    mbar_arrive_rank0(sb + SM_FULL0 + s * 8);
                }
            }
        }
    } else if (wid == 9 && rank == 0) {
        // ---- mma warp (leader CTA only) -------------------------------------
        if (elect1()) {
            for (int kt = 0; kt < NTILES; kt++) {
                const int s = kt & 3;
                const int q = kt >> 2;
                mbar_wait(sb + SM_FULL0 + s * 8, q & 1);
                const uint32_t stg = sb + SM_STAGE0 + s * STAGE_BYTES;
                uint64_t ad = DESC_BASE_SW128 | ((stg >> 4) & 0x3FFF);
                uint64_t bd = DESC_BASE_SW128 | (((stg + SM_BOFF) >> 4) & 0x3FFF);
#pragma unroll
                for (int ks = 0; ks < 4; ks++) {
                    mma_f16_cg2(tmem_base,
                                ad + ks * 2,
                                bd + ks * 2,
                                IDESC_CG2,
                                (kt > 0 || ks > 0) ? 1u : 0u);
                }
                const uint32_t bar = (kt == NTILES - 1) ? (sb + SM_FINAL)
                                                        : (sb + SM_EMPTY0 + s * 8);
                asm volatile(
                    "tcgen05.commit.cta_group::2.mbarrier::arrive::one.shared::cluster.multicast::cluster.b64 [%0], %1;"
                    :: "r"(bar), "h"((uint16_t)3) : "memory");
            }
        }
    }

    // -------- epilogue: each CTA reads its own 128 rows x 256 cols -----------
    mbar_wait(sb + SM_FINAL, 0);
    asm volatile("tcgen05.fence::after_thread_sync;" ::: "memory");

    const int dt = g_dtype;
    if (wid < 8) {
        const int sub = wid & 3;
        const int nh  = wid >> 2;         // 0/1 -> cols 0-127 / 128-255
        const int row = m0 + (int)rank * 128 + sub * 32 + lane;
#pragma unroll
        for (int ch = 0; ch < 4; ch++) {
            uint32_t r[32];
            asm volatile(
                "tcgen05.ld.sync.aligned.32x32b.x32.b32 "
                "{%0,%1,%2,%3,%4,%5,%6,%7,%8,%9,%10,%11,%12,%13,%14,%15,"
                "%16,%17,%18,%19,%20,%21,%22,%23,%24,%25,%26,%27,%28,%29,%30,%31}, [%32];"
                : "=r"(r[0]),  "=r"(r[1]),  "=r"(r[2]),  "=r"(r[3]),
                  "=r"(r[4]),  "=r"(r[5]),  "=r"(r[6]),  "=r"(r[7]),
                  "=r"(r[8]),  "=r"(r[9]),  "=r"(r[10]), "=r"(r[11]),
                  "=r"(r[12]), "=r"(r[13]), "=r"(r[14]), "=r"(r[15]),
                  "=r"(r[16]), "=r"(r[17]), "=r"(r[18]), "=r"(r[19]),
                  "=r"(r[20]), "=r"(r[21]), "=r"(r[22]), "=r"(r[23]),
                  "=r"(r[24]), "=r"(r[25]), "=r"(r[26]), "=r"(r[27]),
                  "=r"(r[28]), "=r"(r[29]), "=r"(r[30]), "=r"(r[31])
                : "r"(tmem_base + nh * 128 + ch * 32));
            asm volatile("tcgen05.wait::ld.sync.aligned;" ::: "memory");

            const int col0 = n0 + nh * 128 + ch * 32;
            if (dt == 1) {
                const float* bf = (const float*)biasv;
                float* of = (float*)outv;
#pragma unroll
                for (int i = 0; i < 32; i += 2) {
                    __half2 hb = __floats2half2_rn(bf[col0 + i], bf[col0 + i + 1]);
                    __half2 hv = __floats2half2_rn(__uint_as_float(r[i]),
                                                   __uint_as_float(r[i + 1]));
                    __half2 ho = __hadd2(hv, hb);
                    of[(size_t)row * NDIM + col0 + i]     = __half2float(__low2half(ho));
                    of[(size_t)row * NDIM + col0 + i + 1] = __half2float(__high2half(ho));
                }
            } else if (dt == 2) {
                const __nv_bfloat16* bb = (const __nv_bfloat16*)biasv;
                __nv_bfloat16* ob = (__nv_bfloat16*)outv;
#pragma unroll
                for (int i = 0; i < 32; i += 2) {
                    __half2 hb = __floats2half2_rn(__bfloat162float(bb[col0 + i]),
                                                   __bfloat162float(bb[col0 + i + 1]));
                    __half2 hv = __floats2half2_rn(__uint_as_float(r[i]),
                                                   __uint_as_float(r[i + 1]));
                    __half2 ho = __hadd2(hv, hb);
                    ob[(size_t)row * NDIM + col0 + i] =
                        __float2bfloat16(__half2float(__low2half(ho)));
                    ob[(size_t)row * NDIM + col0 + i + 1] =
                        __float2bfloat16(__half2float(__high2half(ho)));
                }
            } else {
                const __half* bh = (const __half*)biasv;
                __half* oh = (__half*)outv;
#pragma unroll
                for (int i = 0; i < 32; i += 2) {
                    __half2 hb = *(const __half2*)(bh + col0 + i);
                    __half2 hv = __floats2half2_rn(__uint_as_float(r[i]),
                                                   __uint_as_float(r[i + 1]));
                    *(__half2*)(oh + (size_t)row * NDIM + col0 + i) = __hadd2(hv, hb);
                }
            }
        }
        asm volatile("tcgen05.fence::before_thread_sync;" ::: "memory");
    }

    __syncthreads();
    if (wid == 8) {
        asm volatile("tcgen05.relinquish_alloc_permit.cta_group::2.sync.aligned;");
        asm volatile("tcgen05.dealloc.cta_group::2.sync.aligned.b32 %0, %1;"
                     :: "r"(tmem_base), "r"((uint32_t)TMEM_COLS));
    }
    asm volatile("barrier.cluster.arrive.aligned;" ::: "memory");
    asm volatile("barrier.cluster.wait.aligned;" ::: "memory");
#endif  // TC_PATH
}

// ---------------------------------------------------------------- launch
typedef CUresult (*EncodeTiledFn)(
    CUtensorMap*, CUtensorMapDataType, cuuint32_t, void*,
    const cuuint64_t*, const cuuint64_t*, const cuuint32_t*, const cuuint32_t*,
    CUtensorMapInterleave, CUtensorMapSwizzle, CUtensorMapL2promotion,
    CUtensorMapFloatOOBfill);

extern "C" void kernel_launch(void* const* d_in, const int* in_sizes, int n_in,
                              void* d_out, int out_size)
{
    const void* x    = d_in[0];
    const int*  pw   = (const int*)d_in[1];
    const void* bias = d_in[2];
    for (int i = 0; i < n_in; i++) {
        if      (in_sizes[i] == MDIM * KDIM) x    = d_in[i];
        else if (in_sizes[i] == NDIM * KW)   pw   = (const int*)d_in[i];
        else if (in_sizes[i] == NDIM)        bias = d_in[i];
    }

    cudaFuncSetAttribute(crystal_hmma_kernel,
                         cudaFuncAttributeMaxDynamicSharedMemorySize, HSMEM_BYTES);
    cudaFuncSetAttribute(crystal_tc_kernel,
                         cudaFuncAttributeMaxDynamicSharedMemorySize, SMEM_TOTAL);

    // TMA descriptor for g_x16: box 64 x 128 (BK x rows/CTA), SW128
    CUtensorMap tmap;
    {
        void* fn = nullptr;
        cudaDriverEntryPointQueryResult st;
        cudaGetDriverEntryPoint("cuTensorMapEncodeTiled", &fn,
                                cudaEnableDefault, &st);
        void* xptr = nullptr;
        cudaGetSymbolAddress(&xptr, g_x16);
        cuuint64_t dims[2]    = {KDIM, MDIM};
        cuuint64_t strides[1] = {KDIM * 2};
        cuuint32_t box[2]     = {64, 128};
        cuuint32_t es[2]      = {1, 1};
        if (fn) {
            ((EncodeTiledFn)fn)(&tmap, CU_TENSOR_MAP_DATA_TYPE_FLOAT16, 2, xptr,
                                dims, strides, box, es,
                                CU_TENSOR_MAP_INTERLEAVE_NONE,
                                CU_TENSOR_MAP_SWIZZLE_128B,
                                CU_TENSOR_MAP_L2_PROMOTION_L2_128B,
                                CU_TENSOR_MAP_FLOAT_OOB_FILL_NONE);
        }
    }

    detect_dtype_kernel<<<1, 32>>>((const uint32_t*)x);
    convert_x_kernel<<<MDIM * KDIM / 8 / 256, 256>>>(x);

    dim3 hgrid(NDIM / HBN, MDIM / HBM);   // (64, 8)
    crystal_hmma_kernel<<<hgrid, HNTH, HSMEM_BYTES>>>(pw, bias, d_out);

    dim3 tgrid(8, 32);                    // 256 CTAs = 128 clusters of 2
    crystal_tc_kernel<<<tgrid, NTH, SMEM_TOTAL>>>(tmap, pw, bias, d_out);
}

// round 14
// speedup vs baseline: 1.1034x; 1.1034x over previous
#include <cuda_runtime.h>
#include <cuda_fp16.h>
#include <cuda_bf16.h>
#include <cstdint>

#define MDIM 1024
#define KDIM 8192
#define NDIM 8192
#define KW   512

#if defined(__CUDA_ARCH__) && (defined(__CUDA_ARCH_FEAT_SM103_ALL) || \
                               defined(__CUDA_ARCH_FEAT_SM100_ALL) || \
     (defined(__CUDA_ARCH_FAMILY_SPECIFIC__) && (__CUDA_ARCH_FAMILY_SPECIFIC__ >= 1000)))
#define TC_PATH 1
#else
#define TC_PATH 0
#endif

__device__ int g_dtype;                                        // 0=fp16 1=fp32 2=bf16
__device__ __align__(128) __half g_x16[(size_t)MDIM * KDIM];   // 16 MB

// ---------------------------------------------------------------- helpers
__device__ __forceinline__ uint32_t smem_u32(const void* p) {
    uint32_t a;
    asm("{ .reg .u64 t; cvta.to.shared.u64 t, %1; cvt.u32.u64 %0, t; }"
        : "=r"(a) : "l"(p));
    return a;
}
__device__ __forceinline__ void cpa16(uint32_t dst, const void* src) {
    asm volatile("cp.async.cg.shared.global [%0], [%1], 16;" :: "r"(dst), "l"(src));
}

// ---------------------------------------------------------------- pre-passes
__global__ void detect_dtype_kernel(const uint32_t* __restrict__ xw) {
    int lane = threadIdx.x & 31;
    int cntA = 0, cntB = 0;
    for (int i = lane; i < 1024; i += 32) {
        uint32_t b1 = (xw[i] >> 8) & 0x7Fu;
        cntA += (b1 >= 0x18u && b1 <= 0x4Cu) ? 1 : 0;
        cntB += (b1 >= 0x3Bu && b1 <= 0x41u) ? 1 : 0;
    }
#pragma unroll
    for (int o = 16; o; o >>= 1) {
        cntA += __shfl_down_sync(0xFFFFFFFFu, cntA, o);
        cntB += __shfl_down_sync(0xFFFFFFFFu, cntB, o);
    }
    if (lane == 0) {
        int dt;
        if (cntA < 768)      dt = 1;
        else if (cntB > 716) dt = 2;
        else                 dt = 0;
        g_dtype = dt;
    }
}

__global__ void __launch_bounds__(256)
convert_x_kernel(const void* __restrict__ xv) {
    int dt = g_dtype;
    size_t base = ((size_t)blockIdx.x * 256 + threadIdx.x) * 8;
    uint4 o;
    if (dt == 0) {
        o = *(const uint4*)((const __half*)xv + base);
    } else if (dt == 1) {
        const float4* f = (const float4*)xv;
        float4 v0 = f[base / 4], v1 = f[base / 4 + 1];
        __half2 h0 = __floats2half2_rn(v0.x, v0.y), h1 = __floats2half2_rn(v0.z, v0.w);
        __half2 h2 = __floats2half2_rn(v1.x, v1.y), h3 = __floats2half2_rn(v1.z, v1.w);
        o = make_uint4(*(uint32_t*)&h0, *(uint32_t*)&h1,
                       *(uint32_t*)&h2, *(uint32_t*)&h3);
    } else {
        uint4 bi = *(const uint4*)((const __nv_bfloat16*)xv + base);
        const __nv_bfloat16* bb = (const __nv_bfloat16*)&bi;
        __align__(16) __half hvx[8];
#pragma unroll
        for (int j = 0; j < 8; j++) hvx[j] = __float2half_rn(__bfloat162float(bb[j]));
        o = *(uint4*)hvx;
    }
    *(uint4*)&g_x16[base] = o;
}

// decode one packed word -> 8 uint32 (16 fp16) via PRMT
__device__ __forceinline__ void decode_word(uint32_t vv, uint32_t* hv) {
#pragma unroll
    for (int i = 0; i < 8; i++) {
        uint32_t t = vv >> (4 * i);
        uint32_t sel = 0x0404u | ((t & 3u) << 4) | ((t & 12u) << 10);
        hv[i] = __byte_perm(0x42003C00u, 0u, sel);   // 0->0x00 1->0x3C 3->0x42
    }
}

// ============================================================================
// Path A: legacy HMMA fallback (plain-sm_103 device pass only)
// ============================================================================
#define HBM 128
#define HBN 128
#define HBK 64
#define HNTH 256
#define LDSH 72
#define HSMEM_BYTES 73728

__global__ void __launch_bounds__(HNTH, 2)
crystal_hmma_kernel(const int* __restrict__ pw, const void* __restrict__ biasv,
                    void* __restrict__ outv)
{
#if !TC_PATH
    extern __shared__ char dynsmem[];
    __half* As = (__half*)dynsmem;
    __half* Bs = As + 2 * HBM * LDSH;

    const int tid  = threadIdx.x;
    const int lane = tid & 31;
    const int warp = tid >> 5;
    const int wm   = warp & 1;
    const int wn   = warp >> 1;

    const int m0 = blockIdx.y * HBM;
    const int n0 = blockIdx.x * HBN;

    const uint32_t as_base = smem_u32(As);
    const uint32_t bs_base = smem_u32(Bs);

    const int brow  = tid >> 1;
    const int bpair = tid & 1;

    float acc[4][4][4];
#pragma unroll
    for (int i = 0; i < 4; i++)
#pragma unroll
        for (int j = 0; j < 4; j++)
#pragma unroll
            for (int r = 0; r < 4; r++) acc[i][j][r] = 0.f;

    int2 bst;

#define H_LOAD_A(buf, kt)                                                         \
    {                                                                             \
        _Pragma("unroll")                                                         \
        for (int p = 0; p < 4; p++) {                                             \
            int idx = tid + p * HNTH;                                             \
            int row = idx >> 3, c = idx & 7;                                      \
            const __half* srcA = g_x16 + (size_t)(m0 + row) * KDIM + (kt) * HBK + c * 8; \
            uint32_t dstA = as_base + (uint32_t)((((buf) * HBM + row) * LDSH + c * 8) * 2); \
            cpa16(dstA, srcA);                                                    \
        }                                                                         \
        asm volatile("cp.async.commit_group;");                                   \
    }

#define H_DECODE_B(buf)                                                           \
    {                                                                             \
        uint32_t vals[2] = { (uint32_t)bst.x, (uint32_t)bst.y };                  \
        _Pragma("unroll")                                                         \
        for (int w = 0; w < 2; w++) {                                             \
            uint32_t hv[8];                                                       \
            decode_word(vals[w], hv);                                             \
            uint4* dst = (uint4*)(Bs + (((buf) * HBN + brow) * LDSH + bpair * 32 + w * 16)); \
            dst[0] = make_uint4(hv[0], hv[1], hv[2], hv[3]);                      \
            dst[1] = make_uint4(hv[4], hv[5], hv[6], hv[7]);                      \
        }                                                                         \
    }

#define H_LOAD_B(kt) \
    bst = *(const int2*)(pw + (size_t)(n0 + brow) * KW + (kt) * 4 + bpair * 2);

    H_LOAD_B(0);
    H_LOAD_A(0, 0);
    H_DECODE_B(0);
    asm volatile("cp.async.wait_group 0;");
    __syncthreads();

    const int NK = KDIM / HBK;
    for (int kt = 0; kt < NK; kt++) {
        const int buf = kt & 1;
        const bool nxt = (kt + 1 < NK);
        if (nxt) {
            H_LOAD_A(buf ^ 1, kt + 1);
            H_LOAD_B(kt + 1);
        }

        const int mbase = wm * 64;
        const int nbase = wn * 32;
#pragma unroll
        for (int ks = 0; ks < 4; ks++) {
            uint32_t a[4][4];
#pragma unroll
            for (int mi = 0; mi < 4; mi++) {
                int row = mbase + mi * 16 + (lane & 15);
                int col = ks * 16 + ((lane >> 4) << 3);
                uint32_t addr = as_base + (uint32_t)(((buf * HBM + row) * LDSH + col) * 2);
                asm volatile(
                    "ldmatrix.sync.aligned.m8n8.x4.shared.b16 {%0,%1,%2,%3}, [%4];"
                    : "=r"(a[mi][0]), "=r"(a[mi][1]), "=r"(a[mi][2]), "=r"(a[mi][3])
                    : "r"(addr) : "memory");
            }
            uint32_t b[4][2];
#pragma unroll
            for (int ni = 0; ni < 2; ni++) {
                int q = lane >> 3, r = lane & 7;
                int row = nbase + ni * 16 + ((q >> 1) << 3) + r;
                int col = ks * 16 + ((q & 1) << 3);
                uint32_t addr = bs_base + (uint32_t)(((buf * HBN + row) * LDSH + col) * 2);
                uint32_t r0, r1, r2, r3;
                asm volatile(
                    "ldmatrix.sync.aligned.m8n8.x4.shared.b16 {%0,%1,%2,%3}, [%4];"
                    : "=r"(r0), "=r"(r1), "=r"(r2), "=r"(r3)
                    : "r"(addr) : "memory");
                b[2 * ni][0] = r0;     b[2 * ni][1] = r1;
                b[2 * ni + 1][0] = r2; b[2 * ni + 1][1] = r3;
            }
#pragma unroll
            for (int mi = 0; mi < 4; mi++) {
#pragma unroll
                for (int nj = 0; nj < 4; nj++) {
                    asm volatile(
                        "mma.sync.aligned.m16n8k16.row.col.f32.f16.f16.f32 "
                        "{%0,%1,%2,%3}, {%4,%5,%6,%7}, {%8,%9}, {%0,%1,%2,%3};"
                        : "+f"(acc[mi][nj][0]), "+f"(acc[mi][nj][1]),
                          "+f"(acc[mi][nj][2]), "+f"(acc[mi][nj][3])
                        : "r"(a[mi][0]), "r"(a[mi][1]), "r"(a[mi][2]), "r"(a[mi][3]),
                          "r"(b[nj][0]), "r"(b[nj][1]));
                }
            }
        }
        if (nxt) {
            H_DECODE_B(buf ^ 1);
            asm volatile("cp.async.wait_group 0;");
        }
        __syncthreads();
    }

    const int dt = g_dtype;
    const int g  = lane >> 2;
    const int tq = lane & 3;
#pragma unroll
    for (int nj = 0; nj < 4; nj++) {
        int ncol = n0 + wn * 32 + nj * 8 + tq * 2;
        __half hb0, hb1;
        if (dt == 1) {
            hb0 = __float2half_rn(((const float*)biasv)[ncol]);
            hb1 = __float2half_rn(((const float*)biasv)[ncol + 1]);
        } else if (dt == 2) {
            hb0 = __float2half_rn(__bfloat162float(((const __nv_bfloat16*)biasv)[ncol]));
            hb1 = __float2half_rn(__bfloat162float(((const __nv_bfloat16*)biasv)[ncol + 1]));
        } else {
            __half2 b2 = *(const __half2*)((const __half*)biasv + ncol);
            hb0 = __low2half(b2); hb1 = __high2half(b2);
        }
#pragma unroll
        for (int mi = 0; mi < 4; mi++) {
            int r0 = m0 + wm * 64 + mi * 16 + g;
#pragma unroll
            for (int hr = 0; hr < 2; hr++) {
                int rr = r0 + hr * 8;
                __half o0 = __hadd(__float2half_rn(acc[mi][nj][hr * 2 + 0]), hb0);
                __half o1 = __hadd(__float2half_rn(acc[mi][nj][hr * 2 + 1]), hb1);
                if (dt == 1) {
                    float* of = (float*)outv;
                    of[(size_t)rr * NDIM + ncol]     = __half2float(o0);
                    of[(size_t)rr * NDIM + ncol + 1] = __half2float(o1);
                } else if (dt == 2) {
                    __nv_bfloat16* ob = (__nv_bfloat16*)outv;
                    ob[(size_t)rr * NDIM + ncol]     = __float2bfloat16(__half2float(o0));
                    ob[(size_t)rr * NDIM + ncol + 1] = __float2bfloat16(__half2float(o1));
                } else {
                    __half* oh = (__half*)outv;
                    *(__half2*)(oh + (size_t)rr * NDIM + ncol) = __halves2half2(o0, o1);
                }
            }
        }
    }
#endif  // !TC_PATH
}

// ============================================================================
// Path B: tcgen05 TS-mode 128x256; A in TMEM ring (prefetched LDG),
// B decoded to smem; leader-only arrives (full count = 20)
// ============================================================================
#define BM 128
#define BN 256
#define BK 64
#define NTILES 128
#define STAGES 4
#define NTH 672                  // 4 A warps + 16 B warps + 1 mma warp

#define SM_TMEMPTR 0
#define SM_FULL0   8             // 4 x 8B
#define SM_EMPTY0  40            // 4 x 8B
#define SM_FINAL   72
#define SM_STAGE0  1024
#define STAGE_BYTES 32768        // B only: 256 rows x 128B
#define SMEM_TOTAL (1024 + STAGES * STAGE_BYTES)   // 132096

#define TMEM_COLS 512
#define TMEM_D    0              // D: 128 lanes x 256 cols fp32
#define TMEM_A0   256            // A stages: 4 x 32 cols (128 x 64 fp16 each)

// kind::f16, fp16 inputs, f32 accum, M=128, N=256
#define IDESC_N256 ((1u << 4) | ((256u / 8u) << 17) | ((128u / 16u) << 24))

static constexpr uint64_t DESC_BASE_SW128 =
    (uint64_t(2) << 61) | (uint64_t(1) << 46) | (uint64_t(64) << 32) | (uint64_t(1) << 16);

#if TC_PATH
__device__ __forceinline__ uint32_t elect1() {
    uint32_t pred;
    asm volatile("{\n\t.reg .pred p;\n\telect.sync _|p, 0xFFFFFFFF;\n\t"
                 "selp.b32 %0, 1, 0, p;\n\t}" : "=r"(pred));
    return pred;
}
__device__ __forceinline__ void mbar_init(uint32_t a, uint32_t c) {
    asm volatile("mbarrier.init.shared.b64 [%0], %1;" :: "r"(a), "r"(c) : "memory");
}
__device__ __forceinline__ void mbar_arrive(uint32_t a) {
    asm volatile("mbarrier.arrive.shared.b64 _, [%0];" :: "r"(a) : "memory");
}
__device__ __forceinline__ void mbar_wait(uint32_t a, uint32_t parity) {
    uint32_t done;
    asm volatile("{\n\t.reg .pred p;\n\t"
                 "mbarrier.try_wait.parity.acquire.cta.shared::cta.b64 p, [%1], %2;\n\t"
                 "selp.b32 %0, 1, 0, p;\n\t}"
                 : "=r"(done) : "r"(a), "r"(parity) : "memory");
    if (!done) {
        asm volatile("{\n\t.reg .pred P1;\n\t"
                     "WL%=:\n\t"
                     "mbarrier.try_wait.parity.acquire.cta.shared::cta.b64 P1, [%0], %1, 0x989680;\n\t"
                     "@P1 bra.uni WD%=;\n\t"
                     "bra.uni WL%=;\n\t"
                     "WD%=:\n\t}"
                     :: "r"(a), "r"(parity) : "memory");
    }
}
// TS-mode mma: A operand in TMEM
__device__ __forceinline__ void mma_f16_ts(uint32_t d, uint32_t a_tmem, uint64_t bd,
                                           uint32_t idesc, uint32_t en) {
    asm volatile("{\n\t.reg .pred p;\n\tsetp.ne.u32 p, %4, 0;\n\t"
                 "tcgen05.mma.cta_group::1.kind::f16 [%0], [%1], %2, %3, {%5,%5,%5,%5}, p;\n\t}"
                 :: "r"(d), "r"(a_tmem), "l"(bd), "r"(idesc), "r"(en), "r"(0u) : "memory");
}
__device__ __forceinline__ void ttst_x32(uint32_t addr, const uint32_t* r) {
    asm volatile(
        "tcgen05.st.sync.aligned.32x32b.x32.b32 [%0], "
        "{%1,%2,%3,%4,%5,%6,%7,%8,%9,%10,%11,%12,%13,%14,%15,%16,"
        "%17,%18,%19,%20,%21,%22,%23,%24,%25,%26,%27,%28,%29,%30,%31,%32};"
        :: "r"(addr),
           "r"(r[0]),  "r"(r[1]),  "r"(r[2]),  "r"(r[3]),
           "r"(r[4]),  "r"(r[5]),  "r"(r[6]),  "r"(r[7]),
           "r"(r[8]),  "r"(r[9]),  "r"(r[10]), "r"(r[11]),
           "r"(r[12]), "r"(r[13]), "r"(r[14]), "r"(r[15]),
           "r"(r[16]), "r"(r[17]), "r"(r[18]), "r"(r[19]),
           "r"(r[20]), "r"(r[21]), "r"(r[22]), "r"(r[23]),
           "r"(r[24]), "r"(r[25]), "r"(r[26]), "r"(r[27]),
           "r"(r[28]), "r"(r[29]), "r"(r[30]), "r"(r[31])
        : "memory");
}
#endif

__global__ void __launch_bounds__(NTH, 1)
crystal_tc_kernel(const int* __restrict__ pw, const void* __restrict__ biasv,
                  void* __restrict__ outv)
{
#if TC_PATH
    extern __shared__ char dynsmem[];
    const uint32_t sb = smem_u32(dynsmem);
    const int tid  = threadIdx.x;
    const int wid  = tid >> 5;
    const int lane = tid & 31;

    const int m0 = blockIdx.x * BM;   // x fast: co-resident CTAs share B slices
    const int n0 = blockIdx.y * BN;

    if (tid == 0) {
#pragma unroll
        for (int s = 0; s < STAGES; s++) {
            mbar_init(sb + SM_FULL0 + s * 8, 20);    // 4 A leaders + 16 B leaders
            mbar_init(sb + SM_EMPTY0 + s * 8, 1);    // mma commit
        }
        mbar_init(sb + SM_FINAL, 1);
    }
    if (wid == 20) {
        asm volatile("tcgen05.alloc.cta_group::1.sync.aligned.shared::cta.b32 [%0], %1;"
                     :: "r"(sb + SM_TMEMPTR), "r"((uint32_t)TMEM_COLS) : "memory");
    }
    __syncthreads();
    uint32_t tmem_base;
    asm volatile("ld.shared.b32 %0, [%1];" : "=r"(tmem_base) : "r"(sb + SM_TMEMPTR));

    if (wid < 4) {
        // ---------------- A producers with register double-buffer -----------
        const int arow = wid * 32 + lane;
        const __half* abase = g_x16 + (size_t)(m0 + arow) * KDIM;
        const uint32_t warp_off = ((uint32_t)wid) << 21;
        uint32_t a[32];
        {
            const uint4* src = (const uint4*)abase;   // tile 0
#pragma unroll
            for (int i = 0; i < 8; i++) {
                uint4 v = src[i];
                a[i * 4 + 0] = v.x; a[i * 4 + 1] = v.y;
                a[i * 4 + 2] = v.z; a[i * 4 + 3] = v.w;
            }
        }
        for (int p = 0; p < NTILES; p++) {
            const int s = p & 3;
            const int q = p >> 2;
            if (p >= STAGES)
                mbar_wait(sb + SM_EMPTY0 + s * 8, (q - 1) & 1);
            ttst_x32(tmem_base + TMEM_A0 + s * 32 + warp_off, a);
            asm volatile("tcgen05.wait::st.sync.aligned;" ::: "memory");
            asm volatile("tcgen05.fence::before_thread_sync;" ::: "memory");
            __syncwarp();
            if (lane == 0) mbar_arrive(sb + SM_FULL0 + s * 8);
            if (p + 1 < NTILES) {
                const uint4* src = (const uint4*)(abase + (p + 1) * BK);
#pragma unroll
                for (int i = 0; i < 8; i++) {
                    uint4 v = src[i];
                    a[i * 4 + 0] = v.x; a[i * 4 + 1] = v.y;
                    a[i * 4 + 2] = v.z; a[i * 4 + 3] = v.w;
                }
            }
        }
    } else if (wid < 20) {
        // ---------------- B producers: 512 threads, 2/row --------------------
        const int bt    = tid - 128;          // 0..511
        const int brow  = bt >> 1;            // 0..255
        const int bpair = bt & 1;
        int2 bcur = *(const int2*)(pw + (size_t)(n0 + brow) * KW + bpair * 2);
        for (int p = 0; p < NTILES; p++) {
            const int s = p & 3;
            const int q = p >> 2;
            int2 bnext = make_int2(0, 0);
            if (p + 1 < NTILES)
                bnext = *(const int2*)(pw + (size_t)(n0 + brow) * KW +
                                       (p + 1) * 4 + bpair * 2);
            if (p >= STAGES)
                mbar_wait(sb + SM_EMPTY0 + s * 8, (q - 1) & 1);
            const uint32_t bbase = sb + SM_STAGE0 + s * STAGE_BYTES + brow * 128;
            const uint32_t vals[2] = { (uint32_t)bcur.x, (uint32_t)bcur.y };
#pragma unroll
            for (int w = 0; w < 2; w++) {
                uint32_t hv[8];
                decode_word(vals[w], hv);
#pragma unroll
                for (int h = 0; h < 2; h++) {
                    int u = bpair * 4 + w * 2 + h;
                    uint32_t dst = bbase + ((u ^ (brow & 7)) << 4);
                    asm volatile("st.shared.v4.b32 [%0], {%1,%2,%3,%4};"
                                 :: "r"(dst), "r"(hv[4*h]), "r"(hv[4*h+1]),
                                    "r"(hv[4*h+2]), "r"(hv[4*h+3]) : "memory");
                }
            }
            asm volatile("fence.proxy.async.shared::cta;" ::: "memory");
            __syncwarp();
            if (lane == 0) mbar_arrive(sb + SM_FULL0 + s * 8);
            bcur = bnext;
        }
    } else if (wid == 20) {
        // ---------------- mma warp ------------------------------------------
        if (elect1()) {
            for (int kt = 0; kt < NTILES; kt++) {
                const int s = kt & 3;
                const int q = kt >> 2;
                mbar_wait(sb + SM_FULL0 + s * 8, q & 1);
                asm volatile("tcgen05.fence::after_thread_sync;" ::: "memory");
                const uint32_t stg = sb + SM_STAGE0 + s * STAGE_BYTES;
                uint64_t bd = DESC_BASE_SW128 | ((stg >> 4) & 0x3FFF);
                const uint32_t a_stage = tmem_base + TMEM_A0 + s * 32;
#pragma unroll
                for (int ks = 0; ks < 4; ks++) {
                    mma_f16_ts(tmem_base + TMEM_D,
                               a_stage + ks * 8,
                               bd + ks * 2,
                               IDESC_N256,
                               (kt > 0 || ks > 0) ? 1u : 0u);
                }
                if (kt == NTILES - 1) {
                    asm volatile(
                        "tcgen05.commit.cta_group::1.mbarrier::arrive::one.shared::cluster.b64 [%0];"
                        :: "r"(sb + SM_FINAL) : "memory");
                } else {
                    asm volatile(
                        "tcgen05.commit.cta_group::1.mbarrier::arrive::one.shared::cluster.b64 [%0];"
                        :: "r"(sb + SM_EMPTY0 + s * 8) : "memory");
                }
            }
        }
    }

    // -------- epilogue: warps 0..15 read D (128 rows x 256 cols) -------------
    mbar_wait(sb + SM_FINAL, 0);
    asm volatile("tcgen05.fence::after_thread_sync;" ::: "memory");

    const int dt = g_dtype;
    if (wid < 16) {
        const int sub = wid & 3;          // TMEM subpartition / row block
        const int qn  = wid >> 2;         // col quarter (64 cols each)
        const int row = m0 + sub * 32 + lane;
#pragma unroll
        for (int ch = 0; ch < 2; ch++) {
            uint32_t r[32];
            asm volatile(
                "tcgen05.ld.sync.aligned.32x32b.x32.b32 "
                "{%0,%1,%2,%3,%4,%5,%6,%7,%8,%9,%10,%11,%12,%13,%14,%15,"
                "%16,%17,%18,%19,%20,%21,%22,%23,%24,%25,%26,%27,%28,%29,%30,%31}, [%32];"
                : "=r"(r[0]),  "=r"(r[1]),  "=r"(r[2]),  "=r"(r[3]),
                  "=r"(r[4]),  "=r"(r[5]),  "=r"(r[6]),  "=r"(r[7]),
                  "=r"(r[8]),  "=r"(r[9]),  "=r"(r[10]), "=r"(r[11]),
                  "=r"(r[12]), "=r"(r[13]), "=r"(r[14]), "=r"(r[15]),
                  "=r"(r[16]), "=r"(r[17]), "=r"(r[18]), "=r"(r[19]),
                  "=r"(r[20]), "=r"(r[21]), "=r"(r[22]), "=r"(r[23]),
                  "=r"(r[24]), "=r"(r[25]), "=r"(r[26]), "=r"(r[27]),
                  "=r"(r[28]), "=r"(r[29]), "=r"(r[30]), "=r"(r[31])
                : "r"(tmem_base + TMEM_D + qn * 64 + ch * 32));
            asm volatile("tcgen05.wait::ld.sync.aligned;" ::: "memory");

            const int col0 = n0 + qn * 64 + ch * 32;
            if (dt == 1) {
                const float* bf = (const float*)biasv;
                float* of = (float*)outv;
#pragma unroll
                for (int i = 0; i < 32; i += 2) {
                    __half2 hb = __floats2half2_rn(bf[col0 + i], bf[col0 + i + 1]);
                    __half2 hv = __floats2half2_rn(__uint_as_float(r[i]),
                                                   __uint_as_float(r[i + 1]));
                    __half2 ho = __hadd2(hv, hb);
                    of[(size_t)row * NDIM + col0 + i]     = __half2float(__low2half(ho));
                    of[(size_t)row * NDIM + col0 + i + 1] = __half2float(__high2half(ho));
                }
            } else if (dt == 2) {
                const __nv_bfloat16* bb = (const __nv_bfloat16*)biasv;
                __nv_bfloat16* ob = (__nv_bfloat16*)outv;
#pragma unroll
                for (int i = 0; i < 32; i += 2) {
                    __half2 hb = __floats2half2_rn(__bfloat162float(bb[col0 + i]),
                                                   __bfloat162float(bb[col0 + i + 1]));
                    __half2 hv = __floats2half2_rn(__uint_as_float(r[i]),
                                                   __uint_as_float(r[i + 1]));
                    __half2 ho = __hadd2(hv, hb);
                    ob[(size_t)row * NDIM + col0 + i] =
                        __float2bfloat16(__half2float(__low2half(ho)));
                    ob[(size_t)row * NDIM + col0 + i + 1] =
                        __float2bfloat16(__half2float(__high2half(ho)));
                }
            } else {
                const __half* bh = (const __half*)biasv;
                __half* oh = (__half*)outv;
#pragma unroll
                for (int i = 0; i < 32; i += 2) {
                    __half2 hb = *(const __half2*)(bh + col0 + i);
                    __half2 hv = __floats2half2_rn(__uint_as_float(r[i]),
                                                   __uint_as_float(r[i + 1]));
                    *(__half2*)(oh + (size_t)row * NDIM + col0 + i) = __hadd2(hv, hb);
                }
            }
        }
        asm volatile("tcgen05.fence::before_thread_sync;" ::: "memory");
    }

    __syncthreads();
    if (wid == 20) {
        asm volatile("tcgen05.relinquish_alloc_permit.cta_group::1.sync.aligned;");
        asm volatile("tcgen05.dealloc.cta_group::1.sync.aligned.b32 %0, %1;"
                     :: "r"(tmem_base), "r"((uint32_t)TMEM_COLS));
    }
#endif  // TC_PATH
}

// ---------------------------------------------------------------- launch
extern "C" void kernel_launch(void* const* d_in, const int* in_sizes, int n_in,
                              void* d_out, int out_size)
{
    const void* x    = d_in[0];
    const int*  pw   = (const int*)d_in[1];
    const void* bias = d_in[2];
    for (int i = 0; i < n_in; i++) {
        if      (in_sizes[i] == MDIM * KDIM) x    = d_in[i];
        else if (in_sizes[i] == NDIM * KW)   pw   = (const int*)d_in[i];
        else if (in_sizes[i] == NDIM)        bias = d_in[i];
    }

    cudaFuncSetAttribute(crystal_hmma_kernel,
                         cudaFuncAttributeMaxDynamicSharedMemorySize, HSMEM_BYTES);
    cudaFuncSetAttribute(crystal_tc_kernel,
                         cudaFuncAttributeMaxDynamicSharedMemorySize, SMEM_TOTAL);

    detect_dtype_kernel<<<1, 32>>>((const uint32_t*)x);
    convert_x_kernel<<<MDIM * KDIM / 8 / 256, 256>>>(x);

    dim3 hgrid(NDIM / HBN, MDIM / HBM);   // (64, 8)
    crystal_hmma_kernel<<<hgrid, HNTH, HSMEM_BYTES>>>(pw, bias, d_out);

    dim3 tgrid(MDIM / BM, NDIM / BN);     // (8, 32)
    crystal_tc_kernel<<<tgrid, NTH, SMEM_TOTAL>>>(pw, bias, d_out);
}

// round 15
// speedup vs baseline: 2.0015x; 1.8140x over previous
#include <cuda_runtime.h>
#include <cuda.h>
#include <cuda_fp16.h>
#include <cuda_bf16.h>
#include <cstdint>

#define MDIM 1024
#define KDIM 8192
#define NDIM 8192
#define KW   512

#if defined(__CUDA_ARCH__) && (defined(__CUDA_ARCH_FEAT_SM103_ALL) || \
                               defined(__CUDA_ARCH_FEAT_SM100_ALL) || \
     (defined(__CUDA_ARCH_FAMILY_SPECIFIC__) && (__CUDA_ARCH_FAMILY_SPECIFIC__ >= 1000)))
#define TC_PATH 1
#else
#define TC_PATH 0
#endif

__device__ int g_dtype;                                        // 0=fp16 1=fp32 2=bf16
__device__ __align__(128) __half g_x16[(size_t)MDIM * KDIM];   // 16 MB

// ---------------------------------------------------------------- helpers
__device__ __forceinline__ uint32_t smem_u32(const void* p) {
    uint32_t a;
    asm("{ .reg .u64 t; cvta.to.shared.u64 t, %1; cvt.u32.u64 %0, t; }"
        : "=r"(a) : "l"(p));
    return a;
}
__device__ __forceinline__ void cpa16(uint32_t dst, const void* src) {
    asm volatile("cp.async.cg.shared.global [%0], [%1], 16;" :: "r"(dst), "l"(src));
}

// ---------------------------------------------------------------- pre-passes
__global__ void detect_dtype_kernel(const uint32_t* __restrict__ xw) {
    int lane = threadIdx.x & 31;
    int cntA = 0, cntB = 0;
    for (int i = lane; i < 1024; i += 32) {
        uint32_t b1 = (xw[i] >> 8) & 0x7Fu;
        cntA += (b1 >= 0x18u && b1 <= 0x4Cu) ? 1 : 0;
        cntB += (b1 >= 0x3Bu && b1 <= 0x41u) ? 1 : 0;
    }
#pragma unroll
    for (int o = 16; o; o >>= 1) {
        cntA += __shfl_down_sync(0xFFFFFFFFu, cntA, o);
        cntB += __shfl_down_sync(0xFFFFFFFFu, cntB, o);
    }
    if (lane == 0) {
        int dt;
        if (cntA < 768)      dt = 1;
        else if (cntB > 716) dt = 2;
        else                 dt = 0;
        g_dtype = dt;
    }
}

__global__ void __launch_bounds__(256)
convert_x_kernel(const void* __restrict__ xv) {
    int dt = g_dtype;
    size_t base = ((size_t)blockIdx.x * 256 + threadIdx.x) * 8;
    uint4 o;
    if (dt == 0) {
        o = *(const uint4*)((const __half*)xv + base);
    } else if (dt == 1) {
        const float4* f = (const float4*)xv;
        float4 v0 = f[base / 4], v1 = f[base / 4 + 1];
        __half2 h0 = __floats2half2_rn(v0.x, v0.y), h1 = __floats2half2_rn(v0.z, v0.w);
        __half2 h2 = __floats2half2_rn(v1.x, v1.y), h3 = __floats2half2_rn(v1.z, v1.w);
        o = make_uint4(*(uint32_t*)&h0, *(uint32_t*)&h1,
                       *(uint32_t*)&h2, *(uint32_t*)&h3);
    } else {
        uint4 bi = *(const uint4*)((const __nv_bfloat16*)xv + base);
        const __nv_bfloat16* bb = (const __nv_bfloat16*)&bi;
        __align__(16) __half hvx[8];
#pragma unroll
        for (int j = 0; j < 8; j++) hvx[j] = __float2half_rn(__bfloat162float(bb[j]));
        o = *(uint4*)hvx;
    }
    *(uint4*)&g_x16[base] = o;
}

// decode one packed word -> 8 uint32 (16 fp16) via PRMT
__device__ __forceinline__ void decode_word(uint32_t vv, uint32_t* hv) {
#pragma unroll
    for (int i = 0; i < 8; i++) {
        uint32_t t = vv >> (4 * i);
        uint32_t sel = 0x0404u | ((t & 3u) << 4) | ((t & 12u) << 10);
        hv[i] = __byte_perm(0x42003C00u, 0u, sel);   // 0->0x00 1->0x3C 3->0x42
    }
}

// ============================================================================
// Path A: legacy HMMA fallback (plain-sm_103 device pass only)
// ============================================================================
#define HBM 128
#define HBN 128
#define HBK 64
#define HNTH 256
#define LDSH 72
#define HSMEM_BYTES 73728

__global__ void __launch_bounds__(HNTH, 2)
crystal_hmma_kernel(const int* __restrict__ pw, const void* __restrict__ biasv,
                    void* __restrict__ outv)
{
#if !TC_PATH
    extern __shared__ char dynsmem[];
    __half* As = (__half*)dynsmem;
    __half* Bs = As + 2 * HBM * LDSH;

    const int tid  = threadIdx.x;
    const int lane = tid & 31;
    const int warp = tid >> 5;
    const int wm   = warp & 1;
    const int wn   = warp >> 1;

    const int m0 = blockIdx.y * HBM;
    const int n0 = blockIdx.x * HBN;

    const uint32_t as_base = smem_u32(As);
    const uint32_t bs_base = smem_u32(Bs);

    const int brow  = tid >> 1;
    const int bpair = tid & 1;

    float acc[4][4][4];
#pragma unroll
    for (int i = 0; i < 4; i++)
#pragma unroll
        for (int j = 0; j < 4; j++)
#pragma unroll
            for (int r = 0; r < 4; r++) acc[i][j][r] = 0.f;

    int2 bst;

#define H_LOAD_A(buf, kt)                                                         \
    {                                                                             \
        _Pragma("unroll")                                                         \
        for (int p = 0; p < 4; p++) {                                             \
            int idx = tid + p * HNTH;                                             \
            int row = idx >> 3, c = idx & 7;                                      \
            const __half* srcA = g_x16 + (size_t)(m0 + row) * KDIM + (kt) * HBK + c * 8; \
            uint32_t dstA = as_base + (uint32_t)((((buf) * HBM + row) * LDSH + c * 8) * 2); \
            cpa16(dstA, srcA);                                                    \
        }                                                                         \
        asm volatile("cp.async.commit_group;");                                   \
    }

#define H_DECODE_B(buf)                                                           \
    {                                                                             \
        uint32_t vals[2] = { (uint32_t)bst.x, (uint32_t)bst.y };                  \
        _Pragma("unroll")                                                         \
        for (int w = 0; w < 2; w++) {                                             \
            uint32_t hv[8];                                                       \
            decode_word(vals[w], hv);                                             \
            uint4* dst = (uint4*)(Bs + (((buf) * HBN + brow) * LDSH + bpair * 32 + w * 16)); \
            dst[0] = make_uint4(hv[0], hv[1], hv[2], hv[3]);                      \
            dst[1] = make_uint4(hv[4], hv[5], hv[6], hv[7]);                      \
        }                                                                         \
    }

#define H_LOAD_B(kt) \
    bst = *(const int2*)(pw + (size_t)(n0 + brow) * KW + (kt) * 4 + bpair * 2);

    H_LOAD_B(0);
    H_LOAD_A(0, 0);
    H_DECODE_B(0);
    asm volatile("cp.async.wait_group 0;");
    __syncthreads();

    const int NK = KDIM / HBK;
    for (int kt = 0; kt < NK; kt++) {
        const int buf = kt & 1;
        const bool nxt = (kt + 1 < NK);
        if (nxt) {
            H_LOAD_A(buf ^ 1, kt + 1);
            H_LOAD_B(kt + 1);
        }

        const int mbase = wm * 64;
        const int nbase = wn * 32;
#pragma unroll
        for (int ks = 0; ks < 4; ks++) {
            uint32_t a[4][4];
#pragma unroll
            for (int mi = 0; mi < 4; mi++) {
                int row = mbase + mi * 16 + (lane & 15);
                int col = ks * 16 + ((lane >> 4) << 3);
                uint32_t addr = as_base + (uint32_t)(((buf * HBM + row) * LDSH + col) * 2);
                asm volatile(
                    "ldmatrix.sync.aligned.m8n8.x4.shared.b16 {%0,%1,%2,%3}, [%4];"
                    : "=r"(a[mi][0]), "=r"(a[mi][1]), "=r"(a[mi][2]), "=r"(a[mi][3])
                    : "r"(addr) : "memory");
            }
            uint32_t b[4][2];
#pragma unroll
            for (int ni = 0; ni < 2; ni++) {
                int q = lane >> 3, r = lane & 7;
                int row = nbase + ni * 16 + ((q >> 1) << 3) + r;
                int col = ks * 16 + ((q & 1) << 3);
                uint32_t addr = bs_base + (uint32_t)(((buf * HBN + row) * LDSH + col) * 2);
                uint32_t r0, r1, r2, r3;
                asm volatile(
                    "ldmatrix.sync.aligned.m8n8.x4.shared.b16 {%0,%1,%2,%3}, [%4];"
                    : "=r"(r0), "=r"(r1), "=r"(r2), "=r"(r3)
                    : "r"(addr) : "memory");
                b[2 * ni][0] = r0;     b[2 * ni][1] = r1;
                b[2 * ni + 1][0] = r2; b[2 * ni + 1][1] = r3;
            }
#pragma unroll
            for (int mi = 0; mi < 4; mi++) {
#pragma unroll
                for (int nj = 0; nj < 4; nj++) {
                    asm volatile(
                        "mma.sync.aligned.m16n8k16.row.col.f32.f16.f16.f32 "
                        "{%0,%1,%2,%3}, {%4,%5,%6,%7}, {%8,%9}, {%0,%1,%2,%3};"
                        : "+f"(acc[mi][nj][0]), "+f"(acc[mi][nj][1]),
                          "+f"(acc[mi][nj][2]), "+f"(acc[mi][nj][3])
                        : "r"(a[mi][0]), "r"(a[mi][1]), "r"(a[mi][2]), "r"(a[mi][3]),
                          "r"(b[nj][0]), "r"(b[nj][1]));
                }
            }
        }
        if (nxt) {
            H_DECODE_B(buf ^ 1);
            asm volatile("cp.async.wait_group 0;");
        }
        __syncthreads();
    }

    const int dt = g_dtype;
    const int g  = lane >> 2;
    const int tq = lane & 3;
#pragma unroll
    for (int nj = 0; nj < 4; nj++) {
        int ncol = n0 + wn * 32 + nj * 8 + tq * 2;
        __half hb0, hb1;
        if (dt == 1) {
            hb0 = __float2half_rn(((const float*)biasv)[ncol]);
            hb1 = __float2half_rn(((const float*)biasv)[ncol + 1]);
        } else if (dt == 2) {
            hb0 = __float2half_rn(__bfloat162float(((const __nv_bfloat16*)biasv)[ncol]));
            hb1 = __float2half_rn(__bfloat162float(((const __nv_bfloat16*)biasv)[ncol + 1]));
        } else {
            __half2 b2 = *(const __half2*)((const __half*)biasv + ncol);
            hb0 = __low2half(b2); hb1 = __high2half(b2);
        }
#pragma unroll
        for (int mi = 0; mi < 4; mi++) {
            int r0 = m0 + wm * 64 + mi * 16 + g;
#pragma unroll
            for (int hr = 0; hr < 2; hr++) {
                int rr = r0 + hr * 8;
                __half o0 = __hadd(__float2half_rn(acc[mi][nj][hr * 2 + 0]), hb0);
                __half o1 = __hadd(__float2half_rn(acc[mi][nj][hr * 2 + 1]), hb1);
                if (dt == 1) {
                    float* of = (float*)outv;
                    of[(size_t)rr * NDIM + ncol]     = __half2float(o0);
                    of[(size_t)rr * NDIM + ncol + 1] = __half2float(o1);
                } else if (dt == 2) {
                    __nv_bfloat16* ob = (__nv_bfloat16*)outv;
                    ob[(size_t)rr * NDIM + ncol]     = __float2bfloat16(__half2float(o0));
                    ob[(size_t)rr * NDIM + ncol + 1] = __float2bfloat16(__half2float(o1));
                } else {
                    __half* oh = (__half*)outv;
                    *(__half2*)(oh + (size_t)rr * NDIM + ncol) = __halves2half2(o0, o1);
                }
            }
        }
    }
#endif  // !TC_PATH
}

// ============================================================================
// Path B: tcgen05 256x256, 3-stage; A via TMA, B via PRMT decode, n256 mma
// ============================================================================
#define BM 256
#define BN 256
#define BK 64
#define NTILES 128
#define STAGES 3
#define NTH 576                  // 16 B warps + mma warp (16) + tma warp (17)

#define SM_TMEMPTR 0
#define SM_FULL0   8
#define SM_EMPTY0  32
#define SM_FINAL   56
#define SM_STAGE0  1024
#define STAGE_BYTES 65536        // A 32KB + B 32KB
#define SM_BOFF    32768
#define SMEM_TOTAL (1024 + STAGES * STAGE_BYTES)   // 197632
#define A_TX_BYTES 32768

#define TMEM_COLS 512
// kind::f16, fp16 inputs, f32 accum, M=128, N=256
#define IDESC_N256 ((1u << 4) | ((256u / 8u) << 17) | ((128u / 16u) << 24))

static constexpr uint64_t DESC_BASE_SW128 =
    (uint64_t(2) << 61) | (uint64_t(1) << 46) | (uint64_t(64) << 32) | (uint64_t(1) << 16);

#if TC_PATH
__device__ __forceinline__ uint32_t elect1() {
    uint32_t pred;
    asm volatile("{\n\t.reg .pred p;\n\telect.sync _|p, 0xFFFFFFFF;\n\t"
                 "selp.b32 %0, 1, 0, p;\n\t}" : "=r"(pred));
    return pred;
}
__device__ __forceinline__ void mbar_init(uint32_t a, uint32_t c) {
    asm volatile("mbarrier.init.shared.b64 [%0], %1;" :: "r"(a), "r"(c) : "memory");
}
__device__ __forceinline__ void mbar_arrive(uint32_t a) {
    asm volatile("mbarrier.arrive.shared.b64 _, [%0];" :: "r"(a) : "memory");
}
__device__ __forceinline__ void mbar_wait(uint32_t a, uint32_t parity) {
    uint32_t done;
    asm volatile("{\n\t.reg .pred p;\n\t"
                 "mbarrier.try_wait.parity.acquire.cta.shared::cta.b64 p, [%1], %2;\n\t"
                 "selp.b32 %0, 1, 0, p;\n\t}"
                 : "=r"(done) : "r"(a), "r"(parity) : "memory");
    if (!done) {
        asm volatile("{\n\t.reg .pred P1;\n\t"
                     "WL%=:\n\t"
                     "mbarrier.try_wait.parity.acquire.cta.shared::cta.b64 P1, [%0], %1, 0x989680;\n\t"
                     "@P1 bra.uni WD%=;\n\t"
                     "bra.uni WL%=;\n\t"
                     "WD%=:\n\t}"
                     :: "r"(a), "r"(parity) : "memory");
    }
}
__device__ __forceinline__ void mma_f16_ss(uint32_t d, uint64_t ad, uint64_t bd,
                                           uint32_t idesc, uint32_t en) {
    asm volatile("{\n\t.reg .pred p;\n\tsetp.ne.u32 p, %4, 0;\n\t"
                 "tcgen05.mma.cta_group::1.kind::f16 [%0], %1, %2, %3, {%5,%5,%5,%5}, p;\n\t}"
                 :: "r"(d), "l"(ad), "l"(bd), "r"(idesc), "r"(en), "r"(0u) : "memory");
}
#endif

__global__ void __launch_bounds__(NTH, 1)
crystal_tc_kernel(const __grid_constant__ CUtensorMap tmap,
                  const int* __restrict__ pw, const void* __restrict__ biasv,
                  void* __restrict__ outv)
{
#if TC_PATH
    extern __shared__ char dynsmem[];
    const uint32_t sb = smem_u32(dynsmem);
    const int tid  = threadIdx.x;
    const int wid  = tid >> 5;
    const int lane = tid & 31;

    const int m0 = blockIdx.x * BM;
    const int n0 = blockIdx.y * BN;

    if (tid == 0) {
#pragma unroll
        for (int s = 0; s < STAGES; s++) {
            mbar_init(sb + SM_FULL0 + s * 8, 17);   // 16 B-warp leaders + TMA expect_tx arrive
            mbar_init(sb + SM_EMPTY0 + s * 8, 1);
        }
        mbar_init(sb + SM_FINAL, 1);
    }
    if (wid == 16) {
        asm volatile("tcgen05.alloc.cta_group::1.sync.aligned.shared::cta.b32 [%0], %1;"
                     :: "r"(sb + SM_TMEMPTR), "r"((uint32_t)TMEM_COLS) : "memory");
    }
    __syncthreads();
    uint32_t tmem_base;
    asm volatile("ld.shared.b32 %0, [%1];" : "=r"(tmem_base) : "r"(sb + SM_TMEMPTR));

    if (tid < 512) {
        // ---------------- B decode producers (warps 0..15), depth-2 prefetch -
        const int brow  = tid >> 1;
        const int bpair = tid & 1;
        const int2* bptr = (const int2*)(pw + (size_t)(n0 + brow) * KW + bpair * 2);
        int2 b0 = bptr[0];                      // tile 0 (int2 stride = KW/2 per... load explicit)
        int2 b1 = *(const int2*)(pw + (size_t)(n0 + brow) * KW + 4 + bpair * 2);
        (void)bptr;

        for (int p = 0; p < NTILES; p++) {
            const int s = p % STAGES;
            const int q = p / STAGES;
            int2 bnew = make_int2(0, 0);
            if (p + 2 < NTILES)
                bnew = *(const int2*)(pw + (size_t)(n0 + brow) * KW +
                                      (p + 2) * 4 + bpair * 2);
            if (p >= STAGES)
                mbar_wait(sb + SM_EMPTY0 + s * 8, (q - 1) & 1);
            const uint32_t bbase = sb + SM_STAGE0 + s * STAGE_BYTES + SM_BOFF + brow * 128;
            const uint32_t vals[2] = { (uint32_t)b0.x, (uint32_t)b0.y };
#pragma unroll
            for (int w = 0; w < 2; w++) {
                uint32_t hv[8];
                decode_word(vals[w], hv);
#pragma unroll
                for (int h = 0; h < 2; h++) {
                    int u = bpair * 4 + w * 2 + h;
                    uint32_t dst = bbase + ((u ^ (brow & 7)) << 4);
                    asm volatile("st.shared.v4.b32 [%0], {%1,%2,%3,%4};"
                                 :: "r"(dst), "r"(hv[4*h]), "r"(hv[4*h+1]),
                                    "r"(hv[4*h+2]), "r"(hv[4*h+3]) : "memory");
                }
            }
            asm volatile("fence.proxy.async.shared::cta;" ::: "memory");
            __syncwarp();
            if (lane == 0) mbar_arrive(sb + SM_FULL0 + s * 8);
            b0 = b1;
            b1 = bnew;
        }
    } else if (wid == 16) {
        // ---------------- mma warp (hoisted per-stage descriptors) -----------
        if (elect1()) {
            uint64_t ad_s[STAGES], bd_s[STAGES];
#pragma unroll
            for (int s = 0; s < STAGES; s++) {
                const uint32_t stg = sb + SM_STAGE0 + s * STAGE_BYTES;
                ad_s[s] = DESC_BASE_SW128 | ((stg >> 4) & 0x3FFF);
                bd_s[s] = DESC_BASE_SW128 | (((stg + SM_BOFF) >> 4) & 0x3FFF);
            }
            for (int kt = 0; kt < NTILES; kt++) {
                const int s = kt % STAGES;
                const int q = kt / STAGES;
                mbar_wait(sb + SM_FULL0 + s * 8, q & 1);
                const uint64_t ad = ad_s[s];
                const uint64_t bd = bd_s[s];
#pragma unroll
                for (int ks = 0; ks < 4; ks++) {
#pragma unroll
                    for (int mh = 0; mh < 2; mh++) {
                        // m128 x n256 x k16: A half-row block, full B tile
                        mma_f16_ss(tmem_base + mh * 256,
                                   ad + mh * 1024 + ks * 2,
                                   bd + ks * 2,
                                   IDESC_N256,
                                   (kt > 0 || ks > 0) ? 1u : 0u);
                    }
                }
                if (kt == NTILES - 1) {
                    asm volatile(
                        "tcgen05.commit.cta_group::1.mbarrier::arrive::one.shared::cluster.b64 [%0];"
                        :: "r"(sb + SM_FINAL) : "memory");
                } else {
                    asm volatile(
                        "tcgen05.commit.cta_group::1.mbarrier::arrive::one.shared::cluster.b64 [%0];"
                        :: "r"(sb + SM_EMPTY0 + s * 8) : "memory");
                }
            }
        }
    } else {
        // ---------------- TMA warp (A tiles) ---------------------------------
        if (elect1()) {
            const uint64_t tm = (uint64_t)&tmap;
            for (int p = 0; p < NTILES; p++) {
                const int s = p % STAGES;
                const int q = p / STAGES;
                if (p >= STAGES)
                    mbar_wait(sb + SM_EMPTY0 + s * 8, (q - 1) & 1);
                const uint32_t full = sb + SM_FULL0 + s * 8;
                asm volatile("mbarrier.arrive.expect_tx.shared.b64 _, [%0], %1;"
                             :: "r"(full), "r"((uint32_t)A_TX_BYTES) : "memory");
                const uint32_t stg = sb + SM_STAGE0 + s * STAGE_BYTES;
                asm volatile(
                    "cp.async.bulk.tensor.2d.shared::cta.global.tile.mbarrier::complete_tx::bytes "
                    "[%0], [%1, {%2, %3}], [%4];"
                    :: "r"(stg), "l"(tm), "r"(p * BK), "r"(m0), "r"(full) : "memory");
            }
        }
    }

    // -------- epilogue ------------------------------------------------------
    mbar_wait(sb + SM_FINAL, 0);
    asm volatile("tcgen05.fence::after_thread_sync;" ::: "memory");

    const int dt = g_dtype;
    if (wid < 16) {
        const int sub = wid & 3;
        const int grp = wid >> 2;
        const int mh  = grp & 1;
        const int nh  = grp >> 1;
        const int tcol = mh * 256 + nh * 128;
        const int row = m0 + mh * 128 + sub * 32 + lane;
#pragma unroll
        for (int ch = 0; ch < 4; ch++) {
            uint32_t r[32];
            asm volatile(
                "tcgen05.ld.sync.aligned.32x32b.x32.b32 "
                "{%0,%1,%2,%3,%4,%5,%6,%7,%8,%9,%10,%11,%12,%13,%14,%15,"
                "%16,%17,%18,%19,%20,%21,%22,%23,%24,%25,%26,%27,%28,%29,%30,%31}, [%32];"
                : "=r"(r[0]),  "=r"(r[1]),  "=r"(r[2]),  "=r"(r[3]),
                  "=r"(r[4]),  "=r"(r[5]),  "=r"(r[6]),  "=r"(r[7]),
                  "=r"(r[8]),  "=r"(r[9]),  "=r"(r[10]), "=r"(r[11]),
                  "=r"(r[12]), "=r"(r[13]), "=r"(r[14]), "=r"(r[15]),
                  "=r"(r[16]), "=r"(r[17]), "=r"(r[18]), "=r"(r[19]),
                  "=r"(r[20]), "=r"(r[21]), "=r"(r[22]), "=r"(r[23]),
                  "=r"(r[24]), "=r"(r[25]), "=r"(r[26]), "=r"(r[27]),
                  "=r"(r[28]), "=r"(r[29]), "=r"(r[30]), "=r"(r[31])
                : "r"(tmem_base + tcol + ch * 32));
            asm volatile("tcgen05.wait::ld.sync.aligned;" ::: "memory");

            const int col0 = n0 + nh * 128 + ch * 32;
            if (dt == 1) {
                const float* bf = (const float*)biasv;
                float* of = (float*)outv;
#pragma unroll
                for (int i = 0; i < 32; i += 2) {
                    __half2 hb = __floats2half2_rn(bf[col0 + i], bf[col0 + i + 1]);
                    __half2 hv = __floats2half2_rn(__uint_as_float(r[i]),
                                                   __uint_as_float(r[i + 1]));
                    __half2 ho = __hadd2(hv, hb);
                    of[(size_t)row * NDIM + col0 + i]     = __half2float(__low2half(ho));
                    of[(size_t)row * NDIM + col0 + i + 1] = __half2float(__high2half(ho));
                }
            } else if (dt == 2) {
                const __nv_bfloat16* bb = (const __nv_bfloat16*)biasv;
                __nv_bfloat16* ob = (__nv_bfloat16*)outv;
#pragma unroll
                for (int i = 0; i < 32; i += 2) {
                    __half2 hb = __floats2half2_rn(__bfloat162float(bb[col0 + i]),
                                                   __bfloat162float(bb[col0 + i + 1]));
                    __half2 hv = __floats2half2_rn(__uint_as_float(r[i]),
                                                   __uint_as_float(r[i + 1]));
                    __half2 ho = __hadd2(hv, hb);
                    ob[(size_t)row * NDIM + col0 + i] =
                        __float2bfloat16(__half2float(__low2half(ho)));
                    ob[(size_t)row * NDIM + col0 + i + 1] =
                        __float2bfloat16(__half2float(__high2half(ho)));
                }
            } else {
                const __half* bh = (const __half*)biasv;
                __half* oh = (__half*)outv;
#pragma unroll
                for (int i = 0; i < 32; i += 2) {
                    __half2 hb = *(const __half2*)(bh + col0 + i);
                    __half2 hv = __floats2half2_rn(__uint_as_float(r[i]),
                                                   __uint_as_float(r[i + 1]));
                    *(__half2*)(oh + (size_t)row * NDIM + col0 + i) = __hadd2(hv, hb);
                }
            }
        }
        asm volatile("tcgen05.fence::before_thread_sync;" ::: "memory");
    }

    __syncthreads();
    if (wid == 16) {
        asm volatile("tcgen05.relinquish_alloc_permit.cta_group::1.sync.aligned;");
        asm volatile("tcgen05.dealloc.cta_group::1.sync.aligned.b32 %0, %1;"
                     :: "r"(tmem_base), "r"((uint32_t)TMEM_COLS));
    }
#endif  // TC_PATH
}

// ---------------------------------------------------------------- launch
typedef CUresult (*EncodeTiledFn)(
    CUtensorMap*, CUtensorMapDataType, cuuint32_t, void*,
    const cuuint64_t*, const cuuint64_t*, const cuuint32_t*, const cuuint32_t*,
    CUtensorMapInterleave, CUtensorMapSwizzle, CUtensorMapL2promotion,
    CUtensorMapFloatOOBfill);

extern "C" void kernel_launch(void* const* d_in, const int* in_sizes, int n_in,
                              void* d_out, int out_size)
{
    const void* x    = d_in[0];
    const int*  pw   = (const int*)d_in[1];
    const void* bias = d_in[2];
    for (int i = 0; i < n_in; i++) {
        if      (in_sizes[i] == MDIM * KDIM) x    = d_in[i];
        else if (in_sizes[i] == NDIM * KW)   pw   = (const int*)d_in[i];
        else if (in_sizes[i] == NDIM)        bias = d_in[i];
    }

    cudaFuncSetAttribute(crystal_hmma_kernel,
                         cudaFuncAttributeMaxDynamicSharedMemorySize, HSMEM_BYTES);
    cudaFuncSetAttribute(crystal_tc_kernel,
                         cudaFuncAttributeMaxDynamicSharedMemorySize, SMEM_TOTAL);

    // Which device pass is compiled in? Empty-body kernels use very few regs.
    cudaFuncAttributes ha{}, ta{};
    cudaFuncGetAttributes(&ha, crystal_hmma_kernel);
    cudaFuncGetAttributes(&ta, crystal_tc_kernel);
    bool run_hmma = ha.numRegs > 32;
    bool run_tc   = ta.numRegs > 32;
    if (!run_hmma && !run_tc) { run_hmma = true; run_tc = true; }  // safety net

    // TMA descriptor for g_x16: box 64 x 256 (BK x BM), SW128
    CUtensorMap tmap;
    {
        void* fn = nullptr;
        cudaDriverEntryPointQueryResult st;
        cudaGetDriverEntryPoint("cuTensorMapEncodeTiled", &fn,
                                cudaEnableDefault, &st);
        void* xptr = nullptr;
        cudaGetSymbolAddress(&xptr, g_x16);
        cuuint64_t dims[2]    = {KDIM, MDIM};
        cuuint64_t strides[1] = {KDIM * 2};
        cuuint32_t box[2]     = {64, 256};
        cuuint32_t es[2]      = {1, 1};
        if (fn) {
            ((EncodeTiledFn)fn)(&tmap, CU_TENSOR_MAP_DATA_TYPE_FLOAT16, 2, xptr,
                                dims, strides, box, es,
                                CU_TENSOR_MAP_INTERLEAVE_NONE,
                                CU_TENSOR_MAP_SWIZZLE_128B,
                                CU_TENSOR_MAP_L2_PROMOTION_L2_128B,
                                CU_TENSOR_MAP_FLOAT_OOB_FILL_NONE);
        }
    }

    detect_dtype_kernel<<<1, 32>>>((const uint32_t*)x);
    convert_x_kernel<<<MDIM * KDIM / 8 / 256, 256>>>(x);

    if (run_hmma) {
        dim3 hgrid(NDIM / HBN, MDIM / HBM);   // (64, 8)
        crystal_hmma_kernel<<<hgrid, HNTH, HSMEM_BYTES>>>(pw, bias, d_out);
    }
    if (run_tc) {
        dim3 tgrid(MDIM / BM, NDIM / BN);     // (4, 32): one wave of 128 CTAs
        crystal_tc_kernel<<<tgrid, NTH, SMEM_TOTAL>>>(tmap, pw, bias, d_out);
    }
}